// round 13
// baseline (speedup 1.0000x reference)
#include <cuda_runtime.h>
#include <cuda_fp16.h>
#include <cuda_bf16.h>
#include <cstdint>

#define BB 8
#define HW 3072
#define KK 9216
#define SZ_PROB (8*18*3072)
#define SZ_BBOX (8*36*3072)
#define OUT_LCLS (SZ_PROB+SZ_BBOX)
#define OUT_LBOX (SZ_PROB+SZ_BBOX+1)
#define NCH 144
#define ASZ 24576              // A tile: 96 rows * 256B (fp16 hi|lo)
#define BSZ 16384              // B tile: 128 rows * 128B (fp16 hi only)
#define STGB (ASZ+BSZ)         // 40960
#define SMEM_HMMA (2*STGB)     // 81920 -> 2 CTAs/SM
// heads gemm (bf16 3-pass, unchanged)
#define NCHH 8
#define ASZH 49152
#define STGH 65536
#define SMEM_HEADS (2*STGH)

// ---------------- device scratch ----------------
__device__ __align__(256) __half g_xhi[(size_t)BB*HW*1024];
__device__ __align__(256) __half g_xlo[(size_t)BB*HW*1024];
__device__ __align__(256) __half g_whi[(size_t)512*KK];
__device__ __align__(256) __nv_bfloat16 g_chi[(size_t)BB*HW*512];   // conv1 hi [m][oc]
__device__ __align__(256) __nv_bfloat16 g_clo[(size_t)BB*HW*512];
__device__ __align__(256) __nv_bfloat16 g_hwhi[64*512];
__device__ __align__(256) __nv_bfloat16 g_hwlo[64*512];
__device__ float g_cls[SZ_PROB];
__device__ float g_acc[3];

// ---------------- PTX helpers ----------------
__device__ __forceinline__ uint32_t smem_u32(const void* p) {
  uint32_t a;
  asm("{ .reg .u64 t; cvta.to.shared.u64 t, %1; cvt.u32.u64 %0, t; }" : "=r"(a) : "l"(p));
  return a;
}
__device__ __forceinline__ void cpa16(uint32_t dst, const void* src, int sz) {
  asm volatile("cp.async.cg.shared.global [%0], [%1], 16, %2;"
               :: "r"(dst), "l"(src), "r"(sz) : "memory");
}
#define CPA_COMMIT asm volatile("cp.async.commit_group;" ::: "memory")
#define CPA_WAIT1  asm volatile("cp.async.wait_group 1;" ::: "memory")
__device__ __forceinline__ void ldsm4(uint32_t* r, uint32_t a) {
  asm volatile("ldmatrix.sync.aligned.m8n8.x4.shared.b16 {%0,%1,%2,%3}, [%4];"
    : "=r"(r[0]), "=r"(r[1]), "=r"(r[2]), "=r"(r[3]) : "r"(a));
}
__device__ __forceinline__ void mma_bf16(float* c, const uint32_t* a, const uint32_t* b) {
  asm volatile("mma.sync.aligned.m16n8k16.row.col.f32.bf16.bf16.f32 "
    "{%0,%1,%2,%3}, {%4,%5,%6,%7}, {%8,%9}, {%0,%1,%2,%3};"
    : "+f"(c[0]), "+f"(c[1]), "+f"(c[2]), "+f"(c[3])
    : "r"(a[0]), "r"(a[1]), "r"(a[2]), "r"(a[3]), "r"(b[0]), "r"(b[1]));
}
__device__ __forceinline__ void mma_f16(float* c, const uint32_t* a, const uint32_t* b) {
  asm volatile("mma.sync.aligned.m16n8k16.row.col.f32.f16.f16.f32 "
    "{%0,%1,%2,%3}, {%4,%5,%6,%7}, {%8,%9}, {%0,%1,%2,%3};"
    : "+f"(c[0]), "+f"(c[1]), "+f"(c[2]), "+f"(c[3])
    : "r"(a[0]), "r"(a[1]), "r"(a[2]), "r"(a[3]), "r"(b[0]), "r"(b[1]));
}

// ---------------- misc ----------------
__device__ __forceinline__ float blockReduceSum(float v) {
  __shared__ float sh[32];
  __syncthreads();
  #pragma unroll
  for (int o = 16; o; o >>= 1) v += __shfl_down_sync(0xffffffffu, v, o);
  int lane = threadIdx.x & 31, wid = threadIdx.x >> 5;
  if (lane == 0) sh[wid] = v;
  __syncthreads();
  int nw = blockDim.x >> 5;
  v = (threadIdx.x < (unsigned)nw) ? sh[threadIdx.x] : 0.f;
  if (wid == 0) {
    #pragma unroll
    for (int o = 16; o; o >>= 1) v += __shfl_down_sync(0xffffffffu, v, o);
  }
  return v;
}

__global__ void k_prep(const float* __restrict__ Wcls, const float* __restrict__ Wbb) {
  int i = blockIdx.x * 256 + threadIdx.x;
  if (i < 3) g_acc[i] = 0.f;
  if (i < 64 * 512) {
    int ch = i >> 9, k = i & 511;
    float v = 0.f;
    if (ch < 18) v = Wcls[ch * 512 + k];
    else if (ch < 54) v = Wbb[(ch - 18) * 512 + k];
    __nv_bfloat16 hi = __float2bfloat16(v);
    __nv_bfloat16 lo = __float2bfloat16(v - __bfloat162float(hi));
    g_hwhi[i] = hi; g_hwlo[i] = lo;
  }
}

// conv weights -> fp16 hi only, [oc][tap*1024+ic]
__global__ void __launch_bounds__(256) k_split_w(const float* __restrict__ Wc) {
  __shared__ float s[KK];
  const int oc = blockIdx.x;
  const int tid = threadIdx.x;
  const float4* src = (const float4*)(Wc + (size_t)oc * KK);
  float4* dst = (float4*)s;
  #pragma unroll
  for (int i = tid; i < KK / 4; i += 256) dst[i] = src[i];
  __syncthreads();
  #pragma unroll
  for (int d = tid; d < KK; d += 256) {
    int tap = d >> 10, ic = d & 1023;
    g_whi[(size_t)oc * KK + d] = __float2half(s[ic * 9 + tap]);
  }
}

// NCHW fp32 -> NHWC fp16 hi/lo, 4B-wide stores
__global__ void k_nhwc(const float* __restrict__ x) {
  __shared__ float t[64][33];
  int s0 = blockIdx.x * 32, ic0 = blockIdx.y * 64, b = blockIdx.z;
  int tx = threadIdx.x, ty = threadIdx.y;  // 32 x 8
  #pragma unroll
  for (int i = 0; i < 8; i++)
    t[ty + i * 8][tx] = x[((size_t)b * 1024 + ic0 + ty + i * 8) * HW + s0 + tx];
  __syncthreads();
  #pragma unroll
  for (int i = 0; i < 4; i++) {
    int sp = ty + 8 * i;
    float v0 = t[2 * tx][sp], v1 = t[2 * tx + 1][sp];
    __half h0 = __float2half(v0);
    __half h1 = __float2half(v1);
    __half l0 = __float2half(v0 - __half2float(h0));
    __half l1 = __float2half(v1 - __half2float(h1));
    size_t o = ((size_t)b * HW + s0 + sp) * 1024 + ic0 + 2 * tx;
    __half2 ph; ph.x = h0; ph.y = h1;
    __half2 pl; pl.x = l0; pl.y = l1;
    *(__half2*)(g_xhi + o) = ph;
    *(__half2*)(g_xlo + o) = pl;
  }
}

// ---------------- HMMA implicit-GEMM conv: 96x128 tile, 2-stage, fp16 2-pass ----------------
__global__ void __launch_bounds__(256, 2) k_hmma(const float* __restrict__ bias) {
  extern __shared__ __align__(1024) char smc[];
  const uint32_t smb = smem_u32(smc);
  const int tid  = threadIdx.x;
  const int lane = tid & 31, wid = tid >> 5;
  const int m0 = blockIdx.x * 96;
  const int n0 = blockIdx.y * 128;
  const int b  = m0 / HW;
  const int s0 = m0 - b * HW;
  const int wm = wid & 1, wn = wid >> 1;   // 2(m) x 4(n) warps, 48x32 per warp

  float acc[3][4][4];
  #pragma unroll
  for (int i = 0; i < 3; i++)
    #pragma unroll
    for (int j = 0; j < 4; j++)
      #pragma unroll
      for (int k = 0; k < 4; k++) acc[i][j][k] = 0.f;

  // A loader: 16 cols (256B row, hi|lo) x 16 row-groups x 6 rows
  const int cA   = tid & 15;
  const int hlA  = cA >> 3;
  const int k16A = cA & 7;
  const int rTA  = tid >> 4;
  // B loader: 8 cols (128B row, hi only) x 32 row-groups x 4 rows
  const int cB  = tid & 7;
  const int rTB = tid >> 3;
  const __half* xsrc = hlA ? g_xlo : g_xhi;

  int hh[6], ww6[6];
  #pragma unroll
  for (int t = 0; t < 6; t++) {
    int sp = s0 + rTA + 16 * t;
    hh[t] = sp / 48; ww6[t] = sp - hh[t] * 48;
  }

  auto issue_chunk = [&](int c) {
    const uint32_t stb = smb + (c & 1) * STGB;
    const int tap = c >> 4;
    const int icb = (c & 15) << 6;
    const int dh = tap / 3 - 1, dw = tap % 3 - 1;
    const int koff = icb + k16A * 8;
    #pragma unroll
    for (int t = 0; t < 6; t++) {
      int row = rTA + 16 * t;
      int gh = hh[t] + dh, gw = ww6[t] + dw;
      bool ok = ((unsigned)gh < 64u) & ((unsigned)gw < 48u);
      int spg = ok ? (gh * 48 + gw) : 0;
      const void* src = xsrc + (((size_t)b * HW + spg) << 10) + koff;
      cpa16(stb + row * 256 + ((cA ^ (row & 7)) << 4), src, ok ? 16 : 0);
    }
    #pragma unroll
    for (int t = 0; t < 4; t++) {
      int row = rTB + 32 * t;
      const void* src = g_whi + (size_t)(n0 + row) * KK + (c << 6) + cB * 8;
      cpa16(stb + ASZ + row * 128 + ((cB ^ (row & 7)) << 4), src, 16);
    }
    CPA_COMMIT;
  };

  issue_chunk(0);

  // fragment addressing (validated mappings)
  const int rowA  = wm * 48 + (lane & 15);
  const int khalf = lane >> 4;
  const int rowB  = wn * 32 + (lane >> 4) * 8 + (lane & 7);
  const int khB   = (lane >> 3) & 1;

  #pragma unroll 1
  for (int c = 0; c < NCH; ++c) {
    if (c + 1 < NCH) issue_chunk(c + 1);
    else CPA_COMMIT;
    CPA_WAIT1;
    __syncthreads();

    const uint32_t aB = smb + (c & 1) * STGB;
    const uint32_t bB = aB + ASZ;
    #pragma unroll
    for (int s = 0; s < 4; s++) {
      uint32_t ah[3][4], al[3][4], bq[2][4];
      {
        #pragma unroll
        for (int mt = 0; mt < 3; mt++) {
          int r = rowA + mt * 16;
          int cH = 2 * s + khalf;
          int cL = 8 + cH;
          ldsm4(ah[mt], aB + r * 256 + ((cH ^ (r & 7)) << 4));
          ldsm4(al[mt], aB + r * 256 + ((cL ^ (r & 7)) << 4));
        }
        #pragma unroll
        for (int ntp = 0; ntp < 2; ntp++) {
          int r = rowB + ntp * 16;
          int cH = 2 * s + khB;
          ldsm4(bq[ntp], bB + r * 128 + ((cH ^ (r & 7)) << 4));
        }
      }
      #pragma unroll
      for (int mt = 0; mt < 3; mt++)
        #pragma unroll
        for (int nt = 0; nt < 4; nt++) {
          const uint32_t* bhF = &bq[nt >> 1][(nt & 1) * 2];
          mma_f16(acc[mt][nt], ah[mt], bhF);
          mma_f16(acc[mt][nt], al[mt], bhF);
        }
    }
    __syncthreads();
  }

  // -------- epilogue: bias+relu, split to bf16 hi/lo, store [m][oc] --------
  __nv_bfloat16* soh = (__nv_bfloat16*)smc;            // [96][136] padded
  __nv_bfloat16* sol = soh + 96 * 136;
  const int g = lane >> 2, tg = lane & 3;
  #pragma unroll
  for (int mt = 0; mt < 3; mt++)
    #pragma unroll
    for (int nt = 0; nt < 4; nt++) {
      int r0 = wm * 48 + mt * 16 + g;
      int c0 = wn * 32 + nt * 8 + tg * 2;
      float bz0 = bias[n0 + c0], bz1 = bias[n0 + c0 + 1];
      #pragma unroll
      for (int rr = 0; rr < 2; rr++) {
        int r = r0 + rr * 8;
        float v0 = fmaxf(acc[mt][nt][rr * 2 + 0] + bz0, 0.f);
        float v1 = fmaxf(acc[mt][nt][rr * 2 + 1] + bz1, 0.f);
        __nv_bfloat16 h0 = __float2bfloat16(v0);
        __nv_bfloat16 h1 = __float2bfloat16(v1);
        __nv_bfloat16 l0 = __float2bfloat16(v0 - __bfloat162float(h0));
        __nv_bfloat16 l1 = __float2bfloat16(v1 - __bfloat162float(h1));
        *(__nv_bfloat162*)(soh + r * 136 + c0) = __nv_bfloat162(h0, h1);
        *(__nv_bfloat162*)(sol + r * 136 + c0) = __nv_bfloat162(l0, l1);
      }
    }
  __syncthreads();
  #pragma unroll 1
  for (int i = tid; i < 96 * 32; i += 256) {
    int row = i >> 5, q = i & 31;
    uint2 vh = *(const uint2*)(soh + row * 136 + q * 4);
    uint2 vl = *(const uint2*)(sol + row * 136 + q * 4);
    size_t gofs = (size_t)(m0 + row) * 512 + n0 + q * 4;
    *(uint2*)(g_chi + gofs) = vh;
    *(uint2*)(g_clo + gofs) = vl;
  }
}

// ---------------- HMMA heads gemm: 192x64 tile, K=512, bf16 3-pass ----------------
__global__ void __launch_bounds__(256) k_headsmma(const float* __restrict__ bcls,
                                                  const float* __restrict__ bbb,
                                                  float* __restrict__ out) {
  extern __shared__ __align__(1024) char smc[];
  const uint32_t smb = smem_u32(smc);
  const int tid  = threadIdx.x;
  const int lane = tid & 31, wid = tid >> 5;
  const int m0 = blockIdx.x * 192;
  const int b  = m0 / HW;
  const int s0 = m0 - b * HW;
  const int wm = wid & 3, wn = wid >> 2;

  float acc[3][4][4];
  #pragma unroll
  for (int i = 0; i < 3; i++)
    #pragma unroll
    for (int j = 0; j < 4; j++)
      #pragma unroll
      for (int k = 0; k < 4; k++) acc[i][j][k] = 0.f;

  const int cA  = tid & 15;
  const int hl  = cA >> 3;
  const int k16 = cA & 7;
  const int rT  = tid >> 4;
  const __nv_bfloat16* asrc = hl ? g_clo : g_chi;
  const __nv_bfloat16* bsrc = hl ? g_hwlo : g_hwhi;

  auto issue_chunk = [&](int c) {
    const uint32_t stb = smb + (c & 1) * STGH;
    const int koff = (c << 6) + k16 * 8;
    #pragma unroll
    for (int t = 0; t < 12; t++) {
      int row = rT + 16 * t;
      const void* src = asrc + (size_t)(m0 + row) * 512 + koff;
      cpa16(stb + row * 256 + ((cA ^ (row & 7)) << 4), src, 16);
    }
    #pragma unroll
    for (int t = 0; t < 4; t++) {
      int row = rT + 16 * t;
      const void* src = bsrc + (size_t)row * 512 + koff;
      cpa16(stb + ASZH + row * 256 + ((cA ^ (row & 7)) << 4), src, 16);
    }
    CPA_COMMIT;
  };

  issue_chunk(0);

  const int rowA  = wm * 48 + (lane & 15);
  const int khalf = lane >> 4;
  const int rowB  = wn * 32 + (lane >> 4) * 8 + (lane & 7);
  const int khB   = (lane >> 3) & 1;

  #pragma unroll 1
  for (int c = 0; c < NCHH; ++c) {
    if (c + 1 < NCHH) issue_chunk(c + 1);
    else CPA_COMMIT;
    CPA_WAIT1;
    __syncthreads();

    const uint32_t aB = smb + (c & 1) * STGH;
    const uint32_t bB = aB + ASZH;
    #pragma unroll
    for (int s = 0; s < 4; s++) {
      uint32_t ah[3][4], al[3][4], bq[2][4], bql[2][4];
      {
        #pragma unroll
        for (int mt = 0; mt < 3; mt++) {
          int r = rowA + mt * 16;
          int cH = 2 * s + khalf;
          int cL = 8 + cH;
          ldsm4(ah[mt], aB + r * 256 + ((cH ^ (r & 7)) << 4));
          ldsm4(al[mt], aB + r * 256 + ((cL ^ (r & 7)) << 4));
        }
        #pragma unroll
        for (int ntp = 0; ntp < 2; ntp++) {
          int r = rowB + ntp * 16;
          int cH = 2 * s + khB;
          int cL = 8 + cH;
          ldsm4(bq[ntp],  bB + r * 256 + ((cH ^ (r & 7)) << 4));
          ldsm4(bql[ntp], bB + r * 256 + ((cL ^ (r & 7)) << 4));
        }
      }
      #pragma unroll
      for (int mt = 0; mt < 3; mt++)
        #pragma unroll
        for (int nt = 0; nt < 4; nt++) {
          const uint32_t* bhF = &bq[nt >> 1][(nt & 1) * 2];
          const uint32_t* blF = &bql[nt >> 1][(nt & 1) * 2];
          mma_bf16(acc[mt][nt], ah[mt], bhF);
          mma_bf16(acc[mt][nt], al[mt], bhF);
          mma_bf16(acc[mt][nt], ah[mt], blF);
        }
    }
    __syncthreads();
  }

  // -------- epilogue: transpose [64 ch][192 m] (pad 196), bias, scatter --------
  float* so = (float*)smc;
  const int g = lane >> 2, tg = lane & 3;
  #pragma unroll
  for (int mt = 0; mt < 3; mt++)
    #pragma unroll
    for (int nt = 0; nt < 4; nt++) {
      int r0 = wm * 48 + mt * 16 + g;
      int c0 = wn * 32 + nt * 8 + tg * 2;
      so[c0 * 196 + r0]            = acc[mt][nt][0];
      so[(c0 + 1) * 196 + r0]      = acc[mt][nt][1];
      so[c0 * 196 + r0 + 8]        = acc[mt][nt][2];
      so[(c0 + 1) * 196 + r0 + 8]  = acc[mt][nt][3];
    }
  __syncthreads();
  #pragma unroll 1
  for (int i = tid; i < 64 * 48; i += 256) {
    int ch = i / 48, mq = i - ch * 48;
    float4 v = *(const float4*)(so + ch * 196 + mq * 4);
    if (ch < 18) {
      float bz = bcls[ch];
      v.x += bz; v.y += bz; v.z += bz; v.w += bz;
      *(float4*)(g_cls + (size_t)(b * 18 + ch) * HW + s0 + mq * 4) = v;
    } else if (ch < 54) {
      float bz = bbb[ch - 18];
      v.x += bz; v.y += bz; v.z += bz; v.w += bz;
      *(float4*)(out + SZ_PROB + (size_t)(b * 36 + (ch - 18)) * HW + s0 + mq * 4) = v;
    }
  }
}

// ---------------- losses ----------------
__global__ void __launch_bounds__(256) k_cls(const int* __restrict__ label,
                                             float* __restrict__ out) {
  int idx = blockIdx.x * 256 + threadIdx.x;
  float nll = 0.f, cnt = 0.f;
  if (idx < BB * 9 * HW) {
    int b = idx / (9 * HW);
    int rem = idx - b * (9 * HW);
    int a = rem / HW;
    int s = rem - a * HW;
    float l0 = g_cls[(size_t)(b * 18 + a) * HW + s];
    float l1 = g_cls[(size_t)(b * 18 + a + 9) * HW + s];
    float mx = fmaxf(l0, l1);
    float e0 = expf(l0 - mx), e1 = expf(l1 - mx);
    float sum = e0 + e1, inv = 1.f / sum;
    out[(size_t)(b * 18 + a) * HW + s] = e0 * inv;
    out[(size_t)(b * 18 + a + 9) * HW + s] = e1 * inv;
    int lb = label[idx];
    if (lb >= 0) {
      float chosen = lb ? l1 : l0;
      nll = -(chosen - mx - logf(sum));
      cnt = 1.f;
    }
  }
  float s1 = blockReduceSum(nll);
  if (threadIdx.x == 0) atomicAdd(&g_acc[0], s1);
  float s2 = blockReduceSum(cnt);
  if (threadIdx.x == 0) atomicAdd(&g_acc[1], s2);
}

__global__ void __launch_bounds__(256) k_box(const float* __restrict__ tgt,
                                             const float* __restrict__ iw,
                                             const float* __restrict__ ow,
                                             const float* __restrict__ bbox) {
  int i = blockIdx.x * 256 + threadIdx.x;
  float v = 0.f;
  if (i < SZ_BBOX) {
    float d = iw[i] * (bbox[i] - tgt[i]);
    float ad = fabsf(d);
    float l = (ad < (1.f / 9.f)) ? d * d * 4.5f : (ad - (1.f / 18.f));
    v = ow[i] * l;
  }
  float s = blockReduceSum(v);
  if (threadIdx.x == 0) atomicAdd(&g_acc[2], s);
}

__global__ void k_fin(float* out) {
  out[OUT_LCLS] = g_acc[0] / fmaxf(g_acc[1], 1.f);
  out[OUT_LBOX] = g_acc[2] * 0.125f;
}

// ---------------- host ----------------
extern "C" void kernel_launch(void* const* d_in, const int* in_sizes, int n_in,
                              void* d_out, int out_size) {
  const float* base_feat = (const float*)d_in[0];
  const float* W_conv = (const float*)d_in[1];
  const float* b_conv = (const float*)d_in[2];
  const float* W_cls  = (const float*)d_in[3];
  const float* b_cls  = (const float*)d_in[4];
  const float* W_bbox = (const float*)d_in[5];
  const float* b_bbox = (const float*)d_in[6];
  const int* rpn_label = (const int*)d_in[7];
  const float* tgt = (const float*)d_in[8];
  const float* iw  = (const float*)d_in[9];
  const float* ow  = (const float*)d_in[10];
  float* out = (float*)d_out;

  static int init = 0;
  if (!init) {
    cudaFuncSetAttribute(k_hmma, cudaFuncAttributeMaxDynamicSharedMemorySize, SMEM_HMMA);
    cudaFuncSetAttribute(k_headsmma, cudaFuncAttributeMaxDynamicSharedMemorySize, SMEM_HEADS);
    init = 1;
  }

  k_prep<<<128, 256>>>(W_cls, W_bbox);
  k_split_w<<<512, 256>>>(W_conv);
  k_nhwc<<<dim3(96, 16, 8), dim3(32, 8)>>>(base_feat);
  k_hmma<<<dim3(256, 4), 256, SMEM_HMMA>>>(b_conv);
  k_headsmma<<<128, 256, SMEM_HEADS>>>(b_cls, b_bbox, out);
  k_cls<<<(BB * 9 * HW + 255) / 256, 256>>>(rpn_label, out);
  k_box<<<(SZ_BBOX + 255) / 256, 256>>>(tgt, iw, ow, out + SZ_PROB);
  k_fin<<<1, 1>>>(out);
}

// round 14
// speedup vs baseline: 2.5704x; 2.5704x over previous
#include <cuda_runtime.h>
#include <cuda_fp16.h>
#include <cuda_bf16.h>
#include <cstdint>

#define BB 8
#define HW 3072
#define KK 9216
#define SZ_PROB (8*18*3072)
#define SZ_BBOX (8*36*3072)
#define OUT_LCLS (SZ_PROB+SZ_BBOX)
#define OUT_LBOX (SZ_PROB+SZ_BBOX+1)
#define NCH 144
#define ASZ 12288              // A tile: 96 rows * 128B (fp16)
#define BSZ 16384              // B tile: 128 rows * 128B (fp16)
#define STGB (ASZ+BSZ)         // 28672
#define SMEM_HMMA (2*STGB)     // 57344 -> 2 CTAs/SM
// heads gemm (bf16 3-pass, unchanged)
#define NCHH 8
#define ASZH 49152
#define STGH 65536
#define SMEM_HEADS (2*STGH)

// ---------------- device scratch ----------------
__device__ __align__(256) __half g_xh[(size_t)BB*HW*1024];
__device__ __align__(256) __half g_wh16[(size_t)512*KK];
__device__ __align__(256) __nv_bfloat16 g_chi[(size_t)BB*HW*512];   // conv1 hi [m][oc]
__device__ __align__(256) __nv_bfloat16 g_clo[(size_t)BB*HW*512];
__device__ __align__(256) __nv_bfloat16 g_hwhi[64*512];
__device__ __align__(256) __nv_bfloat16 g_hwlo[64*512];
__device__ float g_cls[SZ_PROB];
__device__ float g_acc[3];

// ---------------- PTX helpers ----------------
__device__ __forceinline__ uint32_t smem_u32(const void* p) {
  uint32_t a;
  asm("{ .reg .u64 t; cvta.to.shared.u64 t, %1; cvt.u32.u64 %0, t; }" : "=r"(a) : "l"(p));
  return a;
}
__device__ __forceinline__ void cpa16(uint32_t dst, const void* src, int sz) {
  asm volatile("cp.async.cg.shared.global [%0], [%1], 16, %2;"
               :: "r"(dst), "l"(src), "r"(sz) : "memory");
}
#define CPA_COMMIT asm volatile("cp.async.commit_group;" ::: "memory")
#define CPA_WAIT1  asm volatile("cp.async.wait_group 1;" ::: "memory")
__device__ __forceinline__ void ldsm4(uint32_t* r, uint32_t a) {
  asm volatile("ldmatrix.sync.aligned.m8n8.x4.shared.b16 {%0,%1,%2,%3}, [%4];"
    : "=r"(r[0]), "=r"(r[1]), "=r"(r[2]), "=r"(r[3]) : "r"(a));
}
__device__ __forceinline__ void mma_bf16(float* c, const uint32_t* a, const uint32_t* b) {
  asm volatile("mma.sync.aligned.m16n8k16.row.col.f32.bf16.bf16.f32 "
    "{%0,%1,%2,%3}, {%4,%5,%6,%7}, {%8,%9}, {%0,%1,%2,%3};"
    : "+f"(c[0]), "+f"(c[1]), "+f"(c[2]), "+f"(c[3])
    : "r"(a[0]), "r"(a[1]), "r"(a[2]), "r"(a[3]), "r"(b[0]), "r"(b[1]));
}
__device__ __forceinline__ void mma_f16(float* c, const uint32_t* a, const uint32_t* b) {
  asm volatile("mma.sync.aligned.m16n8k16.row.col.f32.f16.f16.f32 "
    "{%0,%1,%2,%3}, {%4,%5,%6,%7}, {%8,%9}, {%0,%1,%2,%3};"
    : "+f"(c[0]), "+f"(c[1]), "+f"(c[2]), "+f"(c[3])
    : "r"(a[0]), "r"(a[1]), "r"(a[2]), "r"(a[3]), "r"(b[0]), "r"(b[1]));
}

// ---------------- misc ----------------
__device__ __forceinline__ float blockReduceSum(float v) {
  __shared__ float sh[32];
  __syncthreads();
  #pragma unroll
  for (int o = 16; o; o >>= 1) v += __shfl_down_sync(0xffffffffu, v, o);
  int lane = threadIdx.x & 31, wid = threadIdx.x >> 5;
  if (lane == 0) sh[wid] = v;
  __syncthreads();
  int nw = blockDim.x >> 5;
  v = (threadIdx.x < (unsigned)nw) ? sh[threadIdx.x] : 0.f;
  if (wid == 0) {
    #pragma unroll
    for (int o = 16; o; o >>= 1) v += __shfl_down_sync(0xffffffffu, v, o);
  }
  return v;
}

__global__ void k_prep(const float* __restrict__ Wcls, const float* __restrict__ Wbb) {
  int i = blockIdx.x * 256 + threadIdx.x;
  if (i < 3) g_acc[i] = 0.f;
  if (i < 64 * 512) {
    int ch = i >> 9, k = i & 511;
    float v = 0.f;
    if (ch < 18) v = Wcls[ch * 512 + k];
    else if (ch < 54) v = Wbb[(ch - 18) * 512 + k];
    __nv_bfloat16 hi = __float2bfloat16(v);
    __nv_bfloat16 lo = __float2bfloat16(v - __bfloat162float(hi));
    g_hwhi[i] = hi; g_hwlo[i] = lo;
  }
}

// conv weights -> fp16, [oc][tap*1024+ic]
__global__ void __launch_bounds__(256) k_split_w(const float* __restrict__ Wc) {
  __shared__ float s[KK];
  const int oc = blockIdx.x;
  const int tid = threadIdx.x;
  const float4* src = (const float4*)(Wc + (size_t)oc * KK);
  float4* dst = (float4*)s;
  #pragma unroll
  for (int i = tid; i < KK / 4; i += 256) dst[i] = src[i];
  __syncthreads();
  #pragma unroll
  for (int d = tid; d < KK; d += 256) {
    int tap = d >> 10, ic = d & 1023;
    g_wh16[(size_t)oc * KK + d] = __float2half(s[ic * 9 + tap]);
  }
}

// NCHW fp32 -> NHWC fp16
__global__ void k_nhwc(const float* __restrict__ x) {
  __shared__ float t[64][33];
  int s0 = blockIdx.x * 32, ic0 = blockIdx.y * 64, b = blockIdx.z;
  int tx = threadIdx.x, ty = threadIdx.y;  // 32 x 8
  #pragma unroll
  for (int i = 0; i < 8; i++)
    t[ty + i * 8][tx] = x[((size_t)b * 1024 + ic0 + ty + i * 8) * HW + s0 + tx];
  __syncthreads();
  #pragma unroll
  for (int i = 0; i < 4; i++) {
    int sp = ty + 8 * i;
    __half2 ph;
    ph.x = __float2half(t[2 * tx][sp]);
    ph.y = __float2half(t[2 * tx + 1][sp]);
    size_t o = ((size_t)b * HW + s0 + sp) * 1024 + ic0 + 2 * tx;
    *(__half2*)(g_xh + o) = ph;
  }
}

// ---------------- HMMA implicit-GEMM conv: 96x128 tile, 2-stage, fp16 1-pass ----------------
__global__ void __launch_bounds__(256, 2) k_hmma(const float* __restrict__ bias) {
  extern __shared__ __align__(1024) char smc[];
  const uint32_t smb = smem_u32(smc);
  const int tid  = threadIdx.x;
  const int lane = tid & 31, wid = tid >> 5;
  const int m0 = blockIdx.x * 96;
  const int n0 = blockIdx.y * 128;
  const int b  = m0 / HW;
  const int s0 = m0 - b * HW;
  const int wm = wid & 1, wn = wid >> 1;   // 2(m) x 4(n) warps, 48x32 per warp

  float acc[3][4][4];
  #pragma unroll
  for (int i = 0; i < 3; i++)
    #pragma unroll
    for (int j = 0; j < 4; j++)
      #pragma unroll
      for (int k = 0; k < 4; k++) acc[i][j][k] = 0.f;

  // loaders: 8 cols (128B row) x 32 row-groups; A rows rT+32t (t<3), B rows rT+32t (t<4)
  const int col = tid & 7;
  const int rT  = tid >> 3;

  int hh[3], ww3[3];
  #pragma unroll
  for (int t = 0; t < 3; t++) {
    int sp = s0 + rT + 32 * t;
    hh[t] = sp / 48; ww3[t] = sp - hh[t] * 48;
  }

  auto issue_chunk = [&](int c) {
    const uint32_t stb = smb + (c & 1) * STGB;
    const int tap = c >> 4;
    const int icb = (c & 15) << 6;
    const int dh = tap / 3 - 1, dw = tap % 3 - 1;
    const int koff = icb + col * 8;
    #pragma unroll
    for (int t = 0; t < 3; t++) {
      int row = rT + 32 * t;
      int gh = hh[t] + dh, gw = ww3[t] + dw;
      bool ok = ((unsigned)gh < 64u) & ((unsigned)gw < 48u);
      int spg = ok ? (gh * 48 + gw) : 0;
      const void* src = g_xh + (((size_t)b * HW + spg) << 10) + koff;
      cpa16(stb + row * 128 + ((col ^ (row & 7)) << 4), src, ok ? 16 : 0);
    }
    #pragma unroll
    for (int t = 0; t < 4; t++) {
      int row = rT + 32 * t;
      const void* src = g_wh16 + (size_t)(n0 + row) * KK + (c << 6) + col * 8;
      cpa16(stb + ASZ + row * 128 + ((col ^ (row & 7)) << 4), src, 16);
    }
    CPA_COMMIT;
  };

  issue_chunk(0);

  // fragment addressing (validated mappings; row stride 128B, cols 0..7)
  const int rowA  = wm * 48 + (lane & 15);
  const int khalf = lane >> 4;
  const int rowB  = wn * 32 + (lane >> 4) * 8 + (lane & 7);
  const int khB   = (lane >> 3) & 1;

  #pragma unroll 1
  for (int c = 0; c < NCH; ++c) {
    if (c + 1 < NCH) issue_chunk(c + 1);
    else CPA_COMMIT;
    CPA_WAIT1;
    __syncthreads();

    const uint32_t aB = smb + (c & 1) * STGB;
    const uint32_t bB = aB + ASZ;
    #pragma unroll
    for (int s = 0; s < 4; s++) {
      uint32_t ah[3][4], bq[2][4];
      {
        #pragma unroll
        for (int mt = 0; mt < 3; mt++) {
          int r = rowA + mt * 16;
          int cH = 2 * s + khalf;
          ldsm4(ah[mt], aB + r * 128 + ((cH ^ (r & 7)) << 4));
        }
        #pragma unroll
        for (int ntp = 0; ntp < 2; ntp++) {
          int r = rowB + ntp * 16;
          int cH = 2 * s + khB;
          ldsm4(bq[ntp], bB + r * 128 + ((cH ^ (r & 7)) << 4));
        }
      }
      #pragma unroll
      for (int mt = 0; mt < 3; mt++)
        #pragma unroll
        for (int nt = 0; nt < 4; nt++) {
          const uint32_t* bhF = &bq[nt >> 1][(nt & 1) * 2];
          mma_f16(acc[mt][nt], ah[mt], bhF);
        }
    }
    __syncthreads();
  }

  // -------- epilogue: bias+relu, split to bf16 hi/lo, store [m][oc] --------
  __nv_bfloat16* soh = (__nv_bfloat16*)smc;            // [96][136] padded
  __nv_bfloat16* sol = soh + 96 * 136;
  const int g = lane >> 2, tg = lane & 3;
  #pragma unroll
  for (int mt = 0; mt < 3; mt++)
    #pragma unroll
    for (int nt = 0; nt < 4; nt++) {
      int r0 = wm * 48 + mt * 16 + g;
      int c0 = wn * 32 + nt * 8 + tg * 2;
      float bz0 = bias[n0 + c0], bz1 = bias[n0 + c0 + 1];
      #pragma unroll
      for (int rr = 0; rr < 2; rr++) {
        int r = r0 + rr * 8;
        float v0 = fmaxf(acc[mt][nt][rr * 2 + 0] + bz0, 0.f);
        float v1 = fmaxf(acc[mt][nt][rr * 2 + 1] + bz1, 0.f);
        __nv_bfloat16 h0 = __float2bfloat16(v0);
        __nv_bfloat16 h1 = __float2bfloat16(v1);
        __nv_bfloat16 l0 = __float2bfloat16(v0 - __bfloat162float(h0));
        __nv_bfloat16 l1 = __float2bfloat16(v1 - __bfloat162float(h1));
        *(__nv_bfloat162*)(soh + r * 136 + c0) = __nv_bfloat162(h0, h1);
        *(__nv_bfloat162*)(sol + r * 136 + c0) = __nv_bfloat162(l0, l1);
      }
    }
  __syncthreads();
  #pragma unroll 1
  for (int i = tid; i < 96 * 32; i += 256) {
    int row = i >> 5, q = i & 31;
    uint2 vh = *(const uint2*)(soh + row * 136 + q * 4);
    uint2 vl = *(const uint2*)(sol + row * 136 + q * 4);
    size_t gofs = (size_t)(m0 + row) * 512 + n0 + q * 4;
    *(uint2*)(g_chi + gofs) = vh;
    *(uint2*)(g_clo + gofs) = vl;
  }
}

// ---------------- HMMA heads gemm: 192x64 tile, K=512, bf16 3-pass ----------------
__global__ void __launch_bounds__(256) k_headsmma(const float* __restrict__ bcls,
                                                  const float* __restrict__ bbb,
                                                  float* __restrict__ out) {
  extern __shared__ __align__(1024) char smc[];
  const uint32_t smb = smem_u32(smc);
  const int tid  = threadIdx.x;
  const int lane = tid & 31, wid = tid >> 5;
  const int m0 = blockIdx.x * 192;
  const int b  = m0 / HW;
  const int s0 = m0 - b * HW;
  const int wm = wid & 3, wn = wid >> 2;

  float acc[3][4][4];
  #pragma unroll
  for (int i = 0; i < 3; i++)
    #pragma unroll
    for (int j = 0; j < 4; j++)
      #pragma unroll
      for (int k = 0; k < 4; k++) acc[i][j][k] = 0.f;

  const int cA  = tid & 15;
  const int hl  = cA >> 3;
  const int k16 = cA & 7;
  const int rT  = tid >> 4;
  const __nv_bfloat16* asrc = hl ? g_clo : g_chi;
  const __nv_bfloat16* bsrc = hl ? g_hwlo : g_hwhi;

  auto issue_chunk = [&](int c) {
    const uint32_t stb = smb + (c & 1) * STGH;
    const int koff = (c << 6) + k16 * 8;
    #pragma unroll
    for (int t = 0; t < 12; t++) {
      int row = rT + 16 * t;
      const void* src = asrc + (size_t)(m0 + row) * 512 + koff;
      cpa16(stb + row * 256 + ((cA ^ (row & 7)) << 4), src, 16);
    }
    #pragma unroll
    for (int t = 0; t < 4; t++) {
      int row = rT + 16 * t;
      const void* src = bsrc + (size_t)row * 512 + koff;
      cpa16(stb + ASZH + row * 256 + ((cA ^ (row & 7)) << 4), src, 16);
    }
    CPA_COMMIT;
  };

  issue_chunk(0);

  const int rowA  = wm * 48 + (lane & 15);
  const int khalf = lane >> 4;
  const int rowB  = wn * 32 + (lane >> 4) * 8 + (lane & 7);
  const int khB   = (lane >> 3) & 1;

  #pragma unroll 1
  for (int c = 0; c < NCHH; ++c) {
    if (c + 1 < NCHH) issue_chunk(c + 1);
    else CPA_COMMIT;
    CPA_WAIT1;
    __syncthreads();

    const uint32_t aB = smb + (c & 1) * STGH;
    const uint32_t bB = aB + ASZH;
    #pragma unroll
    for (int s = 0; s < 4; s++) {
      uint32_t ah[3][4], al[3][4], bq[2][4], bql[2][4];
      {
        #pragma unroll
        for (int mt = 0; mt < 3; mt++) {
          int r = rowA + mt * 16;
          int cH = 2 * s + khalf;
          int cL = 8 + cH;
          ldsm4(ah[mt], aB + r * 256 + ((cH ^ (r & 7)) << 4));
          ldsm4(al[mt], aB + r * 256 + ((cL ^ (r & 7)) << 4));
        }
        #pragma unroll
        for (int ntp = 0; ntp < 2; ntp++) {
          int r = rowB + ntp * 16;
          int cH = 2 * s + khB;
          int cL = 8 + cH;
          ldsm4(bq[ntp],  bB + r * 256 + ((cH ^ (r & 7)) << 4));
          ldsm4(bql[ntp], bB + r * 256 + ((cL ^ (r & 7)) << 4));
        }
      }
      #pragma unroll
      for (int mt = 0; mt < 3; mt++)
        #pragma unroll
        for (int nt = 0; nt < 4; nt++) {
          const uint32_t* bhF = &bq[nt >> 1][(nt & 1) * 2];
          const uint32_t* blF = &bql[nt >> 1][(nt & 1) * 2];
          mma_bf16(acc[mt][nt], ah[mt], bhF);
          mma_bf16(acc[mt][nt], al[mt], bhF);
          mma_bf16(acc[mt][nt], ah[mt], blF);
        }
    }
    __syncthreads();
  }

  // -------- epilogue: transpose [64 ch][192 m] (pad 196), bias, scatter --------
  float* so = (float*)smc;
  const int g = lane >> 2, tg = lane & 3;
  #pragma unroll
  for (int mt = 0; mt < 3; mt++)
    #pragma unroll
    for (int nt = 0; nt < 4; nt++) {
      int r0 = wm * 48 + mt * 16 + g;
      int c0 = wn * 32 + nt * 8 + tg * 2;
      so[c0 * 196 + r0]            = acc[mt][nt][0];
      so[(c0 + 1) * 196 + r0]      = acc[mt][nt][1];
      so[c0 * 196 + r0 + 8]        = acc[mt][nt][2];
      so[(c0 + 1) * 196 + r0 + 8]  = acc[mt][nt][3];
    }
  __syncthreads();
  #pragma unroll 1
  for (int i = tid; i < 64 * 48; i += 256) {
    int ch = i / 48, mq = i - ch * 48;
    float4 v = *(const float4*)(so + ch * 196 + mq * 4);
    if (ch < 18) {
      float bz = bcls[ch];
      v.x += bz; v.y += bz; v.z += bz; v.w += bz;
      *(float4*)(g_cls + (size_t)(b * 18 + ch) * HW + s0 + mq * 4) = v;
    } else if (ch < 54) {
      float bz = bbb[ch - 18];
      v.x += bz; v.y += bz; v.z += bz; v.w += bz;
      *(float4*)(out + SZ_PROB + (size_t)(b * 36 + (ch - 18)) * HW + s0 + mq * 4) = v;
    }
  }
}

// ---------------- losses ----------------
__global__ void __launch_bounds__(256) k_cls(const int* __restrict__ label,
                                             float* __restrict__ out) {
  int idx = blockIdx.x * 256 + threadIdx.x;
  float nll = 0.f, cnt = 0.f;
  if (idx < BB * 9 * HW) {
    int b = idx / (9 * HW);
    int rem = idx - b * (9 * HW);
    int a = rem / HW;
    int s = rem - a * HW;
    float l0 = g_cls[(size_t)(b * 18 + a) * HW + s];
    float l1 = g_cls[(size_t)(b * 18 + a + 9) * HW + s];
    float mx = fmaxf(l0, l1);
    float e0 = expf(l0 - mx), e1 = expf(l1 - mx);
    float sum = e0 + e1, inv = 1.f / sum;
    out[(size_t)(b * 18 + a) * HW + s] = e0 * inv;
    out[(size_t)(b * 18 + a + 9) * HW + s] = e1 * inv;
    int lb = label[idx];
    if (lb >= 0) {
      float chosen = lb ? l1 : l0;
      nll = -(chosen - mx - logf(sum));
      cnt = 1.f;
    }
  }
  float s1 = blockReduceSum(nll);
  if (threadIdx.x == 0) atomicAdd(&g_acc[0], s1);
  float s2 = blockReduceSum(cnt);
  if (threadIdx.x == 0) atomicAdd(&g_acc[1], s2);
}

__global__ void __launch_bounds__(256) k_box(const float* __restrict__ tgt,
                                             const float* __restrict__ iw,
                                             const float* __restrict__ ow,
                                             const float* __restrict__ bbox) {
  int i = blockIdx.x * 256 + threadIdx.x;
  float v = 0.f;
  if (i < SZ_BBOX) {
    float d = iw[i] * (bbox[i] - tgt[i]);
    float ad = fabsf(d);
    float l = (ad < (1.f / 9.f)) ? d * d * 4.5f : (ad - (1.f / 18.f));
    v = ow[i] * l;
  }
  float s = blockReduceSum(v);
  if (threadIdx.x == 0) atomicAdd(&g_acc[2], s);
}

__global__ void k_fin(float* out) {
  out[OUT_LCLS] = g_acc[0] / fmaxf(g_acc[1], 1.f);
  out[OUT_LBOX] = g_acc[2] * 0.125f;
}

// ---------------- host ----------------
extern "C" void kernel_launch(void* const* d_in, const int* in_sizes, int n_in,
                              void* d_out, int out_size) {
  const float* base_feat = (const float*)d_in[0];
  const float* W_conv = (const float*)d_in[1];
  const float* b_conv = (const float*)d_in[2];
  const float* W_cls  = (const float*)d_in[3];
  const float* b_cls  = (const float*)d_in[4];
  const float* W_bbox = (const float*)d_in[5];
  const float* b_bbox = (const float*)d_in[6];
  const int* rpn_label = (const int*)d_in[7];
  const float* tgt = (const float*)d_in[8];
  const float* iw  = (const float*)d_in[9];
  const float* ow  = (const float*)d_in[10];
  float* out = (float*)d_out;

  static int init = 0;
  if (!init) {
    cudaFuncSetAttribute(k_hmma, cudaFuncAttributeMaxDynamicSharedMemorySize, SMEM_HMMA);
    cudaFuncSetAttribute(k_headsmma, cudaFuncAttributeMaxDynamicSharedMemorySize, SMEM_HEADS);
    init = 1;
  }

  k_prep<<<128, 256>>>(W_cls, W_bbox);
  k_split_w<<<512, 256>>>(W_conv);
  k_nhwc<<<dim3(96, 16, 8), dim3(32, 8)>>>(base_feat);
  k_hmma<<<dim3(256, 4), 256, SMEM_HMMA>>>(b_conv);
  k_headsmma<<<128, 256, SMEM_HEADS>>>(b_cls, b_bbox, out);
  k_cls<<<(BB * 9 * HW + 255) / 256, 256>>>(rpn_label, out);
  k_box<<<(SZ_BBOX + 255) / 256, 256>>>(tgt, iw, ow, out + SZ_PROB);
  k_fin<<<1, 1>>>(out);
}

// round 15
// speedup vs baseline: 2.7963x; 1.0879x over previous
#include <cuda_runtime.h>
#include <cuda_fp16.h>
#include <cuda_bf16.h>
#include <cstdint>

#define BB 8
#define HW 3072
#define KK 9216
#define SZ_PROB (8*18*3072)
#define SZ_BBOX (8*36*3072)
#define OUT_LCLS (SZ_PROB+SZ_BBOX)
#define OUT_LBOX (SZ_PROB+SZ_BBOX+1)
#define NCH 72                 // K-chunks of 128
#define ASZ 24576              // A tile: 96 rows * 256B (128 fp16)
#define BSZ 32768              // B tile: 128 rows * 256B
#define STGB (ASZ+BSZ)         // 57344
#define SMEM_HMMA (2*STGB)     // 114688 -> 2 CTAs/SM (R8-validated footprint)
// heads gemm (bf16 3-pass, unchanged)
#define NCHH 8
#define ASZH 49152
#define STGH 65536
#define SMEM_HEADS (2*STGH)

// ---------------- device scratch ----------------
__device__ __align__(256) __half g_xh[(size_t)BB*HW*1024];
__device__ __align__(256) __half g_wh16[(size_t)512*KK];
__device__ __align__(256) __nv_bfloat16 g_chi[(size_t)BB*HW*512];   // conv1 hi [m][oc]
__device__ __align__(256) __nv_bfloat16 g_clo[(size_t)BB*HW*512];
__device__ __align__(256) __nv_bfloat16 g_hwhi[64*512];
__device__ __align__(256) __nv_bfloat16 g_hwlo[64*512];
__device__ float g_cls[SZ_PROB];
__device__ float g_acc[3];

// ---------------- PTX helpers ----------------
__device__ __forceinline__ uint32_t smem_u32(const void* p) {
  uint32_t a;
  asm("{ .reg .u64 t; cvta.to.shared.u64 t, %1; cvt.u32.u64 %0, t; }" : "=r"(a) : "l"(p));
  return a;
}
__device__ __forceinline__ void cpa16(uint32_t dst, const void* src, int sz) {
  asm volatile("cp.async.cg.shared.global [%0], [%1], 16, %2;"
               :: "r"(dst), "l"(src), "r"(sz) : "memory");
}
#define CPA_COMMIT asm volatile("cp.async.commit_group;" ::: "memory")
#define CPA_WAIT1  asm volatile("cp.async.wait_group 1;" ::: "memory")
__device__ __forceinline__ void ldsm4(uint32_t* r, uint32_t a) {
  asm volatile("ldmatrix.sync.aligned.m8n8.x4.shared.b16 {%0,%1,%2,%3}, [%4];"
    : "=r"(r[0]), "=r"(r[1]), "=r"(r[2]), "=r"(r[3]) : "r"(a));
}
__device__ __forceinline__ void mma_bf16(float* c, const uint32_t* a, const uint32_t* b) {
  asm volatile("mma.sync.aligned.m16n8k16.row.col.f32.bf16.bf16.f32 "
    "{%0,%1,%2,%3}, {%4,%5,%6,%7}, {%8,%9}, {%0,%1,%2,%3};"
    : "+f"(c[0]), "+f"(c[1]), "+f"(c[2]), "+f"(c[3])
    : "r"(a[0]), "r"(a[1]), "r"(a[2]), "r"(a[3]), "r"(b[0]), "r"(b[1]));
}
__device__ __forceinline__ void mma_f16(float* c, const uint32_t* a, const uint32_t* b) {
  asm volatile("mma.sync.aligned.m16n8k16.row.col.f32.f16.f16.f32 "
    "{%0,%1,%2,%3}, {%4,%5,%6,%7}, {%8,%9}, {%0,%1,%2,%3};"
    : "+f"(c[0]), "+f"(c[1]), "+f"(c[2]), "+f"(c[3])
    : "r"(a[0]), "r"(a[1]), "r"(a[2]), "r"(a[3]), "r"(b[0]), "r"(b[1]));
}

// ---------------- misc ----------------
__device__ __forceinline__ float blockReduceSum(float v) {
  __shared__ float sh[32];
  __syncthreads();
  #pragma unroll
  for (int o = 16; o; o >>= 1) v += __shfl_down_sync(0xffffffffu, v, o);
  int lane = threadIdx.x & 31, wid = threadIdx.x >> 5;
  if (lane == 0) sh[wid] = v;
  __syncthreads();
  int nw = blockDim.x >> 5;
  v = (threadIdx.x < (unsigned)nw) ? sh[threadIdx.x] : 0.f;
  if (wid == 0) {
    #pragma unroll
    for (int o = 16; o; o >>= 1) v += __shfl_down_sync(0xffffffffu, v, o);
  }
  return v;
}

__global__ void k_prep(const float* __restrict__ Wcls, const float* __restrict__ Wbb) {
  int i = blockIdx.x * 256 + threadIdx.x;
  if (i < 3) g_acc[i] = 0.f;
  if (i < 64 * 512) {
    int ch = i >> 9, k = i & 511;
    float v = 0.f;
    if (ch < 18) v = Wcls[ch * 512 + k];
    else if (ch < 54) v = Wbb[(ch - 18) * 512 + k];
    __nv_bfloat16 hi = __float2bfloat16(v);
    __nv_bfloat16 lo = __float2bfloat16(v - __bfloat162float(hi));
    g_hwhi[i] = hi; g_hwlo[i] = lo;
  }
}

// conv weights -> fp16, [oc][tap*1024+ic]
__global__ void __launch_bounds__(256) k_split_w(const float* __restrict__ Wc) {
  __shared__ float s[KK];
  const int oc = blockIdx.x;
  const int tid = threadIdx.x;
  const float4* src = (const float4*)(Wc + (size_t)oc * KK);
  float4* dst = (float4*)s;
  #pragma unroll
  for (int i = tid; i < KK / 4; i += 256) dst[i] = src[i];
  __syncthreads();
  #pragma unroll
  for (int d = tid; d < KK; d += 256) {
    int tap = d >> 10, ic = d & 1023;
    g_wh16[(size_t)oc * KK + d] = __float2half(s[ic * 9 + tap]);
  }
}

// NCHW fp32 -> NHWC fp16
__global__ void k_nhwc(const float* __restrict__ x) {
  __shared__ float t[64][33];
  int s0 = blockIdx.x * 32, ic0 = blockIdx.y * 64, b = blockIdx.z;
  int tx = threadIdx.x, ty = threadIdx.y;  // 32 x 8
  #pragma unroll
  for (int i = 0; i < 8; i++)
    t[ty + i * 8][tx] = x[((size_t)b * 1024 + ic0 + ty + i * 8) * HW + s0 + tx];
  __syncthreads();
  #pragma unroll
  for (int i = 0; i < 4; i++) {
    int sp = ty + 8 * i;
    __half2 ph;
    ph.x = __float2half(t[2 * tx][sp]);
    ph.y = __float2half(t[2 * tx + 1][sp]);
    size_t o = ((size_t)b * HW + s0 + sp) * 1024 + ic0 + 2 * tx;
    *(__half2*)(g_xh + o) = ph;
  }
}

// ---------------- HMMA implicit-GEMM conv: 96x128 tile, K-chunk 128, 2-stage, fp16 ----------------
__global__ void __launch_bounds__(256, 2) k_hmma(const float* __restrict__ bias) {
  extern __shared__ __align__(1024) char smc[];
  const uint32_t smb = smem_u32(smc);
  const int tid  = threadIdx.x;
  const int lane = tid & 31, wid = tid >> 5;
  const int m0 = blockIdx.x * 96;
  const int n0 = blockIdx.y * 128;
  const int b  = m0 / HW;
  const int s0 = m0 - b * HW;
  const int wm = wid & 1, wn = wid >> 1;   // 2(m) x 4(n) warps, 48x32 per warp

  float acc[3][4][4];
  #pragma unroll
  for (int i = 0; i < 3; i++)
    #pragma unroll
    for (int j = 0; j < 4; j++)
      #pragma unroll
      for (int k = 0; k < 4; k++) acc[i][j][k] = 0.f;

  // loader: 16 cols (256B row) x 16 row-groups; A rows rT+16t (t<6), B rows rT+16t (t<8)
  const int col = tid & 15;
  const int rT  = tid >> 4;

  int hh[6], ww6[6];
  #pragma unroll
  for (int t = 0; t < 6; t++) {
    int sp = s0 + rT + 16 * t;
    hh[t] = sp / 48; ww6[t] = sp - hh[t] * 48;
  }

  auto issue_chunk = [&](int c) {
    const uint32_t stb = smb + (c & 1) * STGB;
    const int tap = c >> 3;
    const int icb = (c & 7) << 7;
    const int dh = tap / 3 - 1, dw = tap % 3 - 1;
    const int koff = icb + col * 8;
    #pragma unroll
    for (int t = 0; t < 6; t++) {
      int row = rT + 16 * t;
      int gh = hh[t] + dh, gw = ww6[t] + dw;
      bool ok = ((unsigned)gh < 64u) & ((unsigned)gw < 48u);
      int spg = ok ? (gh * 48 + gw) : 0;
      const void* src = g_xh + (((size_t)b * HW + spg) << 10) + koff;
      cpa16(stb + row * 256 + ((col ^ (row & 7)) << 4), src, ok ? 16 : 0);
    }
    #pragma unroll
    for (int t = 0; t < 8; t++) {
      int row = rT + 16 * t;
      const void* src = g_wh16 + (size_t)(n0 + row) * KK + (c << 7) + col * 8;
      cpa16(stb + ASZ + row * 256 + ((col ^ (row & 7)) << 4), src, 16);
    }
    CPA_COMMIT;
  };

  issue_chunk(0);

  // fragment addressing (validated mappings; row stride 256B, cols 0..15)
  const int rowA  = wm * 48 + (lane & 15);
  const int khalf = lane >> 4;
  const int rowB  = wn * 32 + (lane >> 4) * 8 + (lane & 7);
  const int khB   = (lane >> 3) & 1;

  #pragma unroll 1
  for (int c = 0; c < NCH; ++c) {
    if (c + 1 < NCH) issue_chunk(c + 1);
    else CPA_COMMIT;
    CPA_WAIT1;
    __syncthreads();

    const uint32_t aB = smb + (c & 1) * STGB;
    const uint32_t bB = aB + ASZ;
    #pragma unroll
    for (int s = 0; s < 8; s++) {
      uint32_t ah[3][4], bq[2][4];
      {
        #pragma unroll
        for (int mt = 0; mt < 3; mt++) {
          int r = rowA + mt * 16;
          int cH = 2 * s + khalf;
          ldsm4(ah[mt], aB + r * 256 + ((cH ^ (r & 7)) << 4));
        }
        #pragma unroll
        for (int ntp = 0; ntp < 2; ntp++) {
          int r = rowB + ntp * 16;
          int cH = 2 * s + khB;
          ldsm4(bq[ntp], bB + r * 256 + ((cH ^ (r & 7)) << 4));
        }
      }
      #pragma unroll
      for (int mt = 0; mt < 3; mt++)
        #pragma unroll
        for (int nt = 0; nt < 4; nt++) {
          const uint32_t* bhF = &bq[nt >> 1][(nt & 1) * 2];
          mma_f16(acc[mt][nt], ah[mt], bhF);
        }
    }
    __syncthreads();
  }

  // -------- epilogue: bias+relu, split to bf16 hi/lo, store [m][oc] --------
  __nv_bfloat16* soh = (__nv_bfloat16*)smc;            // [96][136] padded
  __nv_bfloat16* sol = soh + 96 * 136;
  const int g = lane >> 2, tg = lane & 3;
  #pragma unroll
  for (int mt = 0; mt < 3; mt++)
    #pragma unroll
    for (int nt = 0; nt < 4; nt++) {
      int r0 = wm * 48 + mt * 16 + g;
      int c0 = wn * 32 + nt * 8 + tg * 2;
      float bz0 = bias[n0 + c0], bz1 = bias[n0 + c0 + 1];
      #pragma unroll
      for (int rr = 0; rr < 2; rr++) {
        int r = r0 + rr * 8;
        float v0 = fmaxf(acc[mt][nt][rr * 2 + 0] + bz0, 0.f);
        float v1 = fmaxf(acc[mt][nt][rr * 2 + 1] + bz1, 0.f);
        __nv_bfloat16 h0 = __float2bfloat16(v0);
        __nv_bfloat16 h1 = __float2bfloat16(v1);
        __nv_bfloat16 l0 = __float2bfloat16(v0 - __bfloat162float(h0));
        __nv_bfloat16 l1 = __float2bfloat16(v1 - __bfloat162float(h1));
        *(__nv_bfloat162*)(soh + r * 136 + c0) = __nv_bfloat162(h0, h1);
        *(__nv_bfloat162*)(sol + r * 136 + c0) = __nv_bfloat162(l0, l1);
      }
    }
  __syncthreads();
  #pragma unroll 1
  for (int i = tid; i < 96 * 32; i += 256) {
    int row = i >> 5, q = i & 31;
    uint2 vh = *(const uint2*)(soh + row * 136 + q * 4);
    uint2 vl = *(const uint2*)(sol + row * 136 + q * 4);
    size_t gofs = (size_t)(m0 + row) * 512 + n0 + q * 4;
    *(uint2*)(g_chi + gofs) = vh;
    *(uint2*)(g_clo + gofs) = vl;
  }
}

// ---------------- HMMA heads gemm: 192x64 tile, K=512, bf16 3-pass ----------------
__global__ void __launch_bounds__(256) k_headsmma(const float* __restrict__ bcls,
                                                  const float* __restrict__ bbb,
                                                  float* __restrict__ out) {
  extern __shared__ __align__(1024) char smc[];
  const uint32_t smb = smem_u32(smc);
  const int tid  = threadIdx.x;
  const int lane = tid & 31, wid = tid >> 5;
  const int m0 = blockIdx.x * 192;
  const int b  = m0 / HW;
  const int s0 = m0 - b * HW;
  const int wm = wid & 3, wn = wid >> 2;

  float acc[3][4][4];
  #pragma unroll
  for (int i = 0; i < 3; i++)
    #pragma unroll
    for (int j = 0; j < 4; j++)
      #pragma unroll
      for (int k = 0; k < 4; k++) acc[i][j][k] = 0.f;

  const int cA  = tid & 15;
  const int hl  = cA >> 3;
  const int k16 = cA & 7;
  const int rT  = tid >> 4;
  const __nv_bfloat16* asrc = hl ? g_clo : g_chi;
  const __nv_bfloat16* bsrc = hl ? g_hwlo : g_hwhi;

  auto issue_chunk = [&](int c) {
    const uint32_t stb = smb + (c & 1) * STGH;
    const int koff = (c << 6) + k16 * 8;
    #pragma unroll
    for (int t = 0; t < 12; t++) {
      int row = rT + 16 * t;
      const void* src = asrc + (size_t)(m0 + row) * 512 + koff;
      cpa16(stb + row * 256 + ((cA ^ (row & 7)) << 4), src, 16);
    }
    #pragma unroll
    for (int t = 0; t < 4; t++) {
      int row = rT + 16 * t;
      const void* src = bsrc + (size_t)row * 512 + koff;
      cpa16(stb + ASZH + row * 256 + ((cA ^ (row & 7)) << 4), src, 16);
    }
    CPA_COMMIT;
  };

  issue_chunk(0);

  const int rowA  = wm * 48 + (lane & 15);
  const int khalf = lane >> 4;
  const int rowB  = wn * 32 + (lane >> 4) * 8 + (lane & 7);
  const int khB   = (lane >> 3) & 1;

  #pragma unroll 1
  for (int c = 0; c < NCHH; ++c) {
    if (c + 1 < NCHH) issue_chunk(c + 1);
    else CPA_COMMIT;
    CPA_WAIT1;
    __syncthreads();

    const uint32_t aB = smb + (c & 1) * STGH;
    const uint32_t bB = aB + ASZH;
    #pragma unroll
    for (int s = 0; s < 4; s++) {
      uint32_t ah[3][4], al[3][4], bq[2][4], bql[2][4];
      {
        #pragma unroll
        for (int mt = 0; mt < 3; mt++) {
          int r = rowA + mt * 16;
          int cH = 2 * s + khalf;
          int cL = 8 + cH;
          ldsm4(ah[mt], aB + r * 256 + ((cH ^ (r & 7)) << 4));
          ldsm4(al[mt], aB + r * 256 + ((cL ^ (r & 7)) << 4));
        }
        #pragma unroll
        for (int ntp = 0; ntp < 2; ntp++) {
          int r = rowB + ntp * 16;
          int cH = 2 * s + khB;
          int cL = 8 + cH;
          ldsm4(bq[ntp],  bB + r * 256 + ((cH ^ (r & 7)) << 4));
          ldsm4(bql[ntp], bB + r * 256 + ((cL ^ (r & 7)) << 4));
        }
      }
      #pragma unroll
      for (int mt = 0; mt < 3; mt++)
        #pragma unroll
        for (int nt = 0; nt < 4; nt++) {
          const uint32_t* bhF = &bq[nt >> 1][(nt & 1) * 2];
          const uint32_t* blF = &bql[nt >> 1][(nt & 1) * 2];
          mma_bf16(acc[mt][nt], ah[mt], bhF);
          mma_bf16(acc[mt][nt], al[mt], bhF);
          mma_bf16(acc[mt][nt], ah[mt], blF);
        }
    }
    __syncthreads();
  }

  // -------- epilogue: transpose [64 ch][192 m] (pad 196), bias, scatter --------
  float* so = (float*)smc;
  const int g = lane >> 2, tg = lane & 3;
  #pragma unroll
  for (int mt = 0; mt < 3; mt++)
    #pragma unroll
    for (int nt = 0; nt < 4; nt++) {
      int r0 = wm * 48 + mt * 16 + g;
      int c0 = wn * 32 + nt * 8 + tg * 2;
      so[c0 * 196 + r0]            = acc[mt][nt][0];
      so[(c0 + 1) * 196 + r0]      = acc[mt][nt][1];
      so[c0 * 196 + r0 + 8]        = acc[mt][nt][2];
      so[(c0 + 1) * 196 + r0 + 8]  = acc[mt][nt][3];
    }
  __syncthreads();
  #pragma unroll 1
  for (int i = tid; i < 64 * 48; i += 256) {
    int ch = i / 48, mq = i - ch * 48;
    float4 v = *(const float4*)(so + ch * 196 + mq * 4);
    if (ch < 18) {
      float bz = bcls[ch];
      v.x += bz; v.y += bz; v.z += bz; v.w += bz;
      *(float4*)(g_cls + (size_t)(b * 18 + ch) * HW + s0 + mq * 4) = v;
    } else if (ch < 54) {
      float bz = bbb[ch - 18];
      v.x += bz; v.y += bz; v.z += bz; v.w += bz;
      *(float4*)(out + SZ_PROB + (size_t)(b * 36 + (ch - 18)) * HW + s0 + mq * 4) = v;
    }
  }
}

// ---------------- losses ----------------
__global__ void __launch_bounds__(256) k_cls(const int* __restrict__ label,
                                             float* __restrict__ out) {
  int idx = blockIdx.x * 256 + threadIdx.x;
  float nll = 0.f, cnt = 0.f;
  if (idx < BB * 9 * HW) {
    int b = idx / (9 * HW);
    int rem = idx - b * (9 * HW);
    int a = rem / HW;
    int s = rem - a * HW;
    float l0 = g_cls[(size_t)(b * 18 + a) * HW + s];
    float l1 = g_cls[(size_t)(b * 18 + a + 9) * HW + s];
    float mx = fmaxf(l0, l1);
    float e0 = expf(l0 - mx), e1 = expf(l1 - mx);
    float sum = e0 + e1, inv = 1.f / sum;
    out[(size_t)(b * 18 + a) * HW + s] = e0 * inv;
    out[(size_t)(b * 18 + a + 9) * HW + s] = e1 * inv;
    int lb = label[idx];
    if (lb >= 0) {
      float chosen = lb ? l1 : l0;
      nll = -(chosen - mx - logf(sum));
      cnt = 1.f;
    }
  }
  float s1 = blockReduceSum(nll);
  if (threadIdx.x == 0) atomicAdd(&g_acc[0], s1);
  float s2 = blockReduceSum(cnt);
  if (threadIdx.x == 0) atomicAdd(&g_acc[1], s2);
}

__global__ void __launch_bounds__(256) k_box(const float* __restrict__ tgt,
                                             const float* __restrict__ iw,
                                             const float* __restrict__ ow,
                                             const float* __restrict__ bbox) {
  int i = blockIdx.x * 256 + threadIdx.x;
  float v = 0.f;
  if (i < SZ_BBOX) {
    float d = iw[i] * (bbox[i] - tgt[i]);
    float ad = fabsf(d);
    float l = (ad < (1.f / 9.f)) ? d * d * 4.5f : (ad - (1.f / 18.f));
    v = ow[i] * l;
  }
  float s = blockReduceSum(v);
  if (threadIdx.x == 0) atomicAdd(&g_acc[2], s);
}

__global__ void k_fin(float* out) {
  out[OUT_LCLS] = g_acc[0] / fmaxf(g_acc[1], 1.f);
  out[OUT_LBOX] = g_acc[2] * 0.125f;
}

// ---------------- host ----------------
extern "C" void kernel_launch(void* const* d_in, const int* in_sizes, int n_in,
                              void* d_out, int out_size) {
  const float* base_feat = (const float*)d_in[0];
  const float* W_conv = (const float*)d_in[1];
  const float* b_conv = (const float*)d_in[2];
  const float* W_cls  = (const float*)d_in[3];
  const float* b_cls  = (const float*)d_in[4];
  const float* W_bbox = (const float*)d_in[5];
  const float* b_bbox = (const float*)d_in[6];
  const int* rpn_label = (const int*)d_in[7];
  const float* tgt = (const float*)d_in[8];
  const float* iw  = (const float*)d_in[9];
  const float* ow  = (const float*)d_in[10];
  float* out = (float*)d_out;

  static int init = 0;
  if (!init) {
    cudaFuncSetAttribute(k_hmma, cudaFuncAttributeMaxDynamicSharedMemorySize, SMEM_HMMA);
    cudaFuncSetAttribute(k_headsmma, cudaFuncAttributeMaxDynamicSharedMemorySize, SMEM_HEADS);
    init = 1;
  }

  k_prep<<<128, 256>>>(W_cls, W_bbox);
  k_split_w<<<512, 256>>>(W_conv);
  k_nhwc<<<dim3(96, 16, 8), dim3(32, 8)>>>(base_feat);
  k_hmma<<<dim3(256, 4), 256, SMEM_HMMA>>>(b_conv);
  k_headsmma<<<128, 256, SMEM_HEADS>>>(b_cls, b_bbox, out);
  k_cls<<<(BB * 9 * HW + 255) / 256, 256>>>(rpn_label, out);
  k_box<<<(SZ_BBOX + 255) / 256, 256>>>(tgt, iw, ow, out + SZ_PROB);
  k_fin<<<1, 1>>>(out);
}